// round 6
// baseline (speedup 1.0000x reference)
#include <cuda_runtime.h>

#define DDIM 64
#define NREL 31
#define NE_MAX 100000
#define NU_MAX 50000
#define E_MAX  1000000
#define NZ_MAX 1000000

// ---- scratch (__device__ globals; allocation-free) ----
__device__ float g_sq[NE_MAX * NREL];       // per-(entity, relation) squared norm
__device__ int   g_cntE[NE_MAX];            // head degree counts
__device__ int   g_cntU[NU_MAX];            // user row counts
__device__ int   g_ofsE[NE_MAX + 1];        // CSR offsets (entities)
__device__ int   g_ofsU[NU_MAX + 1];        // CSR offsets (users)
__device__ int   g_curE[NE_MAX];            // fill cursors
__device__ int   g_curU[NU_MAX];
__device__ uint2 g_pe[E_MAX];               // per-edge payload {tail, rel}
__device__ uint2 g_pu[NZ_MAX];              // per-nnz payload {col, val bits}

// ---------------------------------------------------------------------------
__global__ void k_zero_cnt(int n_ent, int n_usr) {
    int i = blockIdx.x * blockDim.x + threadIdx.x;
    if (i < n_ent) g_cntE[i] = 0;
    if (i < n_usr) g_cntU[i] = 0;
}

// Count heads and interact rows in one grid.
__global__ void k_count(const int* __restrict__ head, int n_edges,
                        const int* __restrict__ irow, int nnz) {
    int i = blockIdx.x * blockDim.x + threadIdx.x;
    if (i < n_edges) {
        atomicAdd(&g_cntE[head[i]], 1);
    } else {
        int j = i - n_edges;
        if (j < nnz) atomicAdd(&g_cntU[irow[j]], 1);
    }
}

// Two block-loop exclusive scans: block 0 -> entities, block 1 -> users.
__global__ void k_scan(int n_ent, int n_usr) {
    int* cnt; int* ofs; int* cur; int n;
    if (blockIdx.x == 0) { cnt = g_cntE; ofs = g_ofsE; cur = g_curE; n = n_ent; }
    else                 { cnt = g_cntU; ofs = g_ofsU; cur = g_curU; n = n_usr; }

    __shared__ int wsum[32];
    __shared__ int blocktot;
    int tid = threadIdx.x, lane = tid & 31, wid = tid >> 5;
    int running = 0;

    for (int base = 0; base < n; base += 1024) {
        int i = base + tid;
        int v = (i < n) ? cnt[i] : 0;
        int x = v;
        #pragma unroll
        for (int o = 1; o < 32; o <<= 1) {
            int y = __shfl_up_sync(0xffffffffu, x, o);
            if (lane >= o) x += y;
        }
        if (lane == 31) wsum[wid] = x;
        __syncthreads();
        if (wid == 0) {
            int w = wsum[lane];
            #pragma unroll
            for (int o = 1; o < 32; o <<= 1) {
                int y = __shfl_up_sync(0xffffffffu, w, o);
                if (lane >= o) w += y;
            }
            wsum[lane] = w;
            if (lane == 31) blocktot = w;
        }
        __syncthreads();
        int warpoff = (wid > 0) ? wsum[wid - 1] : 0;
        int excl = running + warpoff + x - v;
        if (i < n) { ofs[i] = excl; cur[i] = excl; }
        running += blocktot;
        __syncthreads();   // wsum/blocktot reused next iteration
    }
    if (tid == 0) ofs[n] = running;
}

// Fill CSR payloads (counting sort).
__global__ void k_fill(const int* __restrict__ head, const int* __restrict__ tail,
                       const int* __restrict__ etype, int n_edges,
                       const int* __restrict__ irow, const int* __restrict__ icol,
                       const float* __restrict__ ival, int nnz) {
    int i = blockIdx.x * blockDim.x + threadIdx.x;
    if (i < n_edges) {
        int h = head[i];
        int pos = atomicAdd(&g_curE[h], 1);
        g_pe[pos] = make_uint2((unsigned)tail[i], (unsigned)(etype[i] - 1));
    } else {
        int j = i - n_edges;
        if (j < nnz) {
            int rr = irow[j];
            int pos = atomicAdd(&g_curU[rr], 1);
            g_pu[pos] = make_uint2((unsigned)icol[j], __float_as_uint(ival[j]));
        }
    }
}

// ---------------------------------------------------------------------------
// g_sq[v, r] = sum_d emb[v,d]^2 * w[r,d]^2   (warp per entity)
__global__ void k_entity_sq(const float* __restrict__ emb,
                            const float* __restrict__ weight, int n_ent) {
    __shared__ float2 w2[NREL * 32];
    for (int i = threadIdx.x; i < NREL * 32; i += blockDim.x) {
        float a = weight[2 * i], b = weight[2 * i + 1];
        w2[i] = make_float2(a * a, b * b);
    }
    __syncthreads();
    int warp = (blockIdx.x * blockDim.x + threadIdx.x) >> 5;
    int lane = threadIdx.x & 31;
    if (warp >= n_ent) return;
    float2 e = reinterpret_cast<const float2*>(emb)[warp * 32 + lane];
    float e0 = e.x * e.x, e1 = e.y * e.y;
    #pragma unroll 4
    for (int r = 0; r < NREL; r++) {
        float2 w = w2[r * 32 + lane];
        float p = e0 * w.x + e1 * w.y;
        #pragma unroll
        for (int o = 16; o; o >>= 1) p += __shfl_xor_sync(0xffffffffu, p, o);
        if (lane == 0) g_sq[warp * NREL + r] = p;
    }
}

// ---------------------------------------------------------------------------
// Warp per head entity: softmax-weighted neighbor aggregation, no atomics.
// entity_agg[h] = (sum_e ex_e * emb[t_e] * w[r_e]) / (sum_e ex_e)
__global__ void k_entity_gather(const float* __restrict__ emb,
                                const float* __restrict__ weight,
                                float* __restrict__ out, int n_ent) {
    __shared__ float2 sw[NREL * 32];
    for (int i = threadIdx.x; i < NREL * 32; i += blockDim.x)
        sw[i] = reinterpret_cast<const float2*>(weight)[i];
    __syncthreads();
    int h = (blockIdx.x * blockDim.x + threadIdx.x) >> 5;
    int lane = threadIdx.x & 31;
    if (h >= n_ent) return;
    int s0 = g_ofsE[h], s1 = g_ofsE[h + 1];
    const float* __restrict__ sqh = &g_sq[h * NREL];
    float ax = 0.0f, ay = 0.0f, ssum = 0.0f;
    for (int p = s0; p < s1; p++) {
        uint2 pe = g_pe[p];                       // broadcast, sequential
        int t = (int)pe.x, r = (int)pe.y;
        float ex = __expf(sqh[r] * g_sq[t * NREL + r]);
        float2 tv = reinterpret_cast<const float2*>(emb)[t * 32 + lane];
        float2 wv = sw[r * 32 + lane];
        ax += ex * tv.x * wv.x;
        ay += ex * tv.y * wv.y;
        ssum += ex;
    }
    float inv = (s1 > s0) ? 1.0f / ssum : 0.0f;
    reinterpret_cast<float2*>(out)[h * 32 + lane] = make_float2(ax * inv, ay * inv);
}

// ---------------------------------------------------------------------------
// Warp per user: SpMM gather + fused softmax-projection epilogue, no atomics.
__global__ void k_user_gather(const float* __restrict__ emb,
                              const float* __restrict__ user_emb,
                              const float* __restrict__ weight,
                              float* __restrict__ out_user, int n_usr) {
    __shared__ float2 sw[NREL * 32];
    for (int i = threadIdx.x; i < NREL * 32; i += blockDim.x)
        sw[i] = reinterpret_cast<const float2*>(weight)[i];
    __syncthreads();
    int u = (blockIdx.x * blockDim.x + threadIdx.x) >> 5;
    int lane = threadIdx.x & 31;
    if (u >= n_usr) return;
    int s0 = g_ofsU[u], s1 = g_ofsU[u + 1];
    float ax = 0.0f, ay = 0.0f;
    for (int p = s0; p < s1; p++) {
        uint2 pu = g_pu[p];
        int c = (int)pu.x;
        float v = __uint_as_float(pu.y);
        float2 ev = reinterpret_cast<const float2*>(emb)[c * 32 + lane];
        ax += v * ev.x;
        ay += v * ev.y;
    }
    // epilogue: score = softmax(u_emb @ W^T); out = ua + (score @ W) * ua
    float2 ue = reinterpret_cast<const float2*>(user_emb)[u * 32 + lane];
    float myLogit = 0.0f;
    for (int r = 0; r < NREL; r++) {
        float2 w = sw[r * 32 + lane];
        float p = ue.x * w.x + ue.y * w.y;
        #pragma unroll
        for (int o = 16; o; o >>= 1) p += __shfl_xor_sync(0xffffffffu, p, o);
        if (lane == r) myLogit = p;
    }
    float v = (lane < NREL) ? myLogit : -3.4e38f;
    float mx = v;
    #pragma unroll
    for (int o = 16; o; o >>= 1) mx = fmaxf(mx, __shfl_xor_sync(0xffffffffu, mx, o));
    float ex = (lane < NREL) ? __expf(myLogit - mx) : 0.0f;
    float sum = ex;
    #pragma unroll
    for (int o = 16; o; o >>= 1) sum += __shfl_xor_sync(0xffffffffu, sum, o);
    float score = ex / sum;
    float prx = 0.0f, pry = 0.0f;
    for (int r = 0; r < NREL; r++) {
        float sr = __shfl_sync(0xffffffffu, score, r);
        float2 w = sw[r * 32 + lane];
        prx += sr * w.x;
        pry += sr * w.y;
    }
    reinterpret_cast<float2*>(out_user)[u * 32 + lane] =
        make_float2(ax + prx * ax, ay + pry * ay);
}

// ---------------------------------------------------------------------------
extern "C" void kernel_launch(void* const* d_in, const int* in_sizes, int n_in,
                              void* d_out, int out_size) {
    const float* entity_emb = (const float*)d_in[0];
    const float* user_emb   = (const float*)d_in[1];
    const int*   edge_index = (const int*)d_in[2];
    const int*   edge_type  = (const int*)d_in[3];
    const int*   irow       = (const int*)d_in[4];
    const int*   icol       = (const int*)d_in[5];
    const float* ival       = (const float*)d_in[6];
    const float* weight     = (const float*)d_in[7];

    int n_ent   = in_sizes[0] / DDIM;
    int n_usr   = in_sizes[1] / DDIM;
    int n_edges = in_sizes[3];
    int nnz     = in_sizes[6];

    float* out      = (float*)d_out;
    float* out_user = out + (long long)n_ent * DDIM;

    const int* head = edge_index;
    const int* tail = edge_index + n_edges;

    int tot = n_edges + nnz;

    k_zero_cnt<<<(n_ent + 255) / 256, 256>>>(n_ent, n_usr);
    k_count<<<(tot + 255) / 256, 256>>>(head, n_edges, irow, nnz);
    k_scan<<<2, 1024>>>(n_ent, n_usr);
    k_fill<<<(tot + 255) / 256, 256>>>(head, tail, edge_type, n_edges,
                                       irow, icol, ival, nnz);
    k_entity_sq<<<(n_ent * 32 + 255) / 256, 256>>>(entity_emb, weight, n_ent);
    k_entity_gather<<<(n_ent * 32 + 255) / 256, 256>>>(entity_emb, weight,
                                                       out, n_ent);
    k_user_gather<<<(n_usr * 32 + 255) / 256, 256>>>(entity_emb, user_emb,
                                                     weight, out_user, n_usr);
}